// round 11
// baseline (speedup 1.0000x reference)
#include <cuda_runtime.h>
#include <cuda_fp16.h>
#include <cstdint>
#include <math.h>

// ---------------------------------------------------------------------------
// SoftEmbRescore (sm_100 base ISA — tcgen05 unavailable in this build):
//   prep:  G = emb @ emb^T (tf32 mma.sync -> fp16 store, blocks 0..63)
//          x_h = fp16(x)   (blocks 64.., overlapped with G)
//          e_norm from diagonal CTAs of G.
//   dots = x_h @ G_h  (fp16 m16n8k16 mma.sync, R7 config: 128x256 CTA,
//          64x64 warp tile, 3-stage cp.async — at the f32-accum HMMA
//          rate ceiling per R7/R9/R10 evidence)
//          + epilogue s^2 partials (s_i^2 = sum_j dots_ij * x_ij, row-local)
//   rowsum: s_i = sqrt(sum of 4 partials)
//   finalize: out = dots / max(s_i * e_j, 1e-8)   (no x re-read)
// ---------------------------------------------------------------------------

namespace {
constexpr int MDIM = 65536;
constexpr int NDIM = 1024;
constexpr int KDIM = 1024;

// ---- main GEMM tiling (fp16, R7 config) ----
constexpr int BM = 128;
constexpr int BN = 256;
constexpr int BK = 64;
constexpr int LDSH = BK + 8;                     // 72 halves = 144 B rows
constexpr int NTHREADS = 256;
constexpr int NSTAGE = 3;
constexpr int NT = KDIM / BK;                    // 16
constexpr int STAGE_HALVES = (BM + BN) * LDSH;   // 27648 halves = 55296 B
constexpr int SMEM_MAIN = NSTAGE * STAGE_HALVES * 2;  // 165888 B
constexpr int NCTA_N = NDIM / BN;                // 4 column partials per row

// ---- G-builder tiling (tf32 mma.sync, 64 CTAs inside prep) ----
constexpr int GBM = 128, GBN = 128, GBK = 16;
constexpr int GLDS = GBK + 4;
constexpr int GNT = KDIM / GBK;
constexpr int GSTAGE = (GBM + GBN) * GLDS;
}

__device__ __align__(16) __half g_h[(size_t)NDIM * NDIM];     // 2 MB
__device__ __align__(16) __half x_h[(size_t)MDIM * KDIM];     // 128 MB
__device__ __align__(16) float e_norm[NDIM];
__device__ __align__(16) float s2_part[NCTA_N][MDIM];         // 1 MB
__device__ __align__(16) float s_row[MDIM];

// ============================ helpers ======================================

__device__ __forceinline__ uint32_t smem_u32(const void* p) {
    uint32_t a;
    asm("{ .reg .u64 t; cvta.to.shared.u64 t, %1; cvt.u32.u64 %0, t; }" : "=r"(a) : "l"(p));
    return a;
}
__device__ __forceinline__ uint32_t f2tf32(float f) {
    uint32_t r;
    asm("cvt.rna.tf32.f32 %0, %1;" : "=r"(r) : "f"(f));
    return r;
}
__device__ __forceinline__ void mma_tf32(float* d, const uint32_t* a, const uint32_t* b) {
    asm volatile(
        "mma.sync.aligned.m16n8k8.row.col.f32.tf32.tf32.f32 "
        "{%0,%1,%2,%3}, {%4,%5,%6,%7}, {%8,%9}, {%0,%1,%2,%3};"
        : "+f"(d[0]), "+f"(d[1]), "+f"(d[2]), "+f"(d[3])
        : "r"(a[0]), "r"(a[1]), "r"(a[2]), "r"(a[3]), "r"(b[0]), "r"(b[1]));
}
__device__ __forceinline__ void mma_f16(float* d, const uint32_t* a, const uint32_t* b) {
    asm volatile(
        "mma.sync.aligned.m16n8k16.row.col.f32.f16.f16.f32 "
        "{%0,%1,%2,%3}, {%4,%5,%6,%7}, {%8,%9}, {%0,%1,%2,%3};"
        : "+f"(d[0]), "+f"(d[1]), "+f"(d[2]), "+f"(d[3])
        : "r"(a[0]), "r"(a[1]), "r"(a[2]), "r"(a[3]), "r"(b[0]), "r"(b[1]));
}

#define CP_ASYNC16(dst, src) \
    asm volatile("cp.async.cg.shared.global [%0], [%1], 16;" :: "r"(dst), "l"(src))
#define CP_COMMIT() asm volatile("cp.async.commit_group;")
#define CP_WAIT2()  asm volatile("cp.async.wait_group 2;")
#define CP_WAIT1()  asm volatile("cp.async.wait_group 1;")
#define CP_WAIT0()  asm volatile("cp.async.wait_group 0;")

// ====== kernel 1: prep = {G-builder (blocks 0..63) | x->fp16 (rest)} =======

__global__ __launch_bounds__(256)
void prep_kernel(const float* __restrict__ emb, const float* __restrict__ x)
{
    __shared__ __align__(16) float smem[2 * GSTAGE];
    const int tid = threadIdx.x;

    if (blockIdx.x >= 64) {
        // -------- cvt path: 8 elems/thread, 2048/block --------
        size_t i = ((size_t)(blockIdx.x - 64) * 256 + tid) * 8;
        float4 v0 = *reinterpret_cast<const float4*>(x + i);
        float4 v1 = *reinterpret_cast<const float4*>(x + i + 4);
        __half2 h[4];
        h[0] = __floats2half2_rn(v0.x, v0.y);
        h[1] = __floats2half2_rn(v0.z, v0.w);
        h[2] = __floats2half2_rn(v1.x, v1.y);
        h[3] = __floats2half2_rn(v1.z, v1.w);
        *reinterpret_cast<uint4*>(x_h + i) = *reinterpret_cast<uint4*>(h);
        return;
    }

    // -------- G path: 64 CTAs, 128x128 tiles --------
    const int m0 = (blockIdx.x >> 3) * GBM;
    const int n0 = (blockIdx.x & 7) * GBN;
    const float* A = emb;

    auto load_stage = [&](int s, int kt) {
        const float* Ag = A + (size_t)m0 * KDIM + kt * GBK;
        const float* Bg = A + (size_t)n0 * KDIM + kt * GBK;
        float* Asm = smem + s * GSTAGE;
        float* Bsm = Asm + GBM * GLDS;
        #pragma unroll
        for (int i = 0; i < 2; ++i) {
            int chunk = tid + i * 256;
            int r = chunk >> 2;
            int c = (chunk & 3) * 4;
            CP_ASYNC16(smem_u32(Asm + r * GLDS + c), Ag + (size_t)r * KDIM + c);
            CP_ASYNC16(smem_u32(Bsm + r * GLDS + c), Bg + (size_t)r * KDIM + c);
        }
        CP_COMMIT();
    };

    const int warp = tid >> 5, lane = tid & 31;
    const int mb = (warp & 3) * 32, nb = (warp >> 2) * 64;
    const int grp = lane >> 2, tig = lane & 3;

    float d[2][8][4];
    #pragma unroll
    for (int mi = 0; mi < 2; ++mi)
        #pragma unroll
        for (int ni = 0; ni < 8; ++ni)
            #pragma unroll
            for (int r = 0; r < 4; ++r) d[mi][ni][r] = 0.f;

    load_stage(0, 0);
    for (int t = 0; t < GNT; ++t) {
        if (t + 1 < GNT) { load_stage((t + 1) & 1, t + 1); CP_WAIT1(); }
        else             { CP_WAIT0(); }
        __syncthreads();
        const float* Asm = smem + (t & 1) * GSTAGE;
        const float* Bsm = Asm + GBM * GLDS;
        #pragma unroll
        for (int kk = 0; kk < GBK; kk += 8) {
            uint32_t a[2][4];
            #pragma unroll
            for (int mi = 0; mi < 2; ++mi) {
                const float* p = Asm + (mb + mi * 16 + grp) * GLDS + kk + tig;
                a[mi][0] = f2tf32(p[0]);
                a[mi][1] = f2tf32(p[8 * GLDS]);
                a[mi][2] = f2tf32(p[4]);
                a[mi][3] = f2tf32(p[8 * GLDS + 4]);
            }
            uint32_t b[8][2];
            #pragma unroll
            for (int ni = 0; ni < 8; ++ni) {
                const float* p = Bsm + (nb + ni * 8 + grp) * GLDS + kk + tig;
                b[ni][0] = f2tf32(p[0]);
                b[ni][1] = f2tf32(p[4]);
            }
            #pragma unroll
            for (int mi = 0; mi < 2; ++mi)
                #pragma unroll
                for (int ni = 0; ni < 8; ++ni)
                    mma_tf32(d[mi][ni], a[mi], b[ni]);
        }
        __syncthreads();
    }
    // store G as fp16 (the exact operand the main GEMM consumes)
    #pragma unroll
    for (int mi = 0; mi < 2; ++mi) {
        #pragma unroll
        for (int ni = 0; ni < 8; ++ni) {
            int row = m0 + mb + mi * 16 + grp;
            int col = n0 + nb + ni * 8 + 2 * tig;
            *reinterpret_cast<__half2*>(g_h + (size_t)row * NDIM + col) =
                __floats2half2_rn(d[mi][ni][0], d[mi][ni][1]);
            *reinterpret_cast<__half2*>(g_h + (size_t)(row + 8) * NDIM + col) =
                __floats2half2_rn(d[mi][ni][2], d[mi][ni][3]);
        }
    }
    // diagonal CTAs also produce e_norm (gmem writes visible in-CTA after sync)
    if (m0 == n0) {
        __syncthreads();
        if (tid < GBM) {
            int j = m0 + tid;
            e_norm[j] = sqrtf(fmaxf(__half2float(g_h[(size_t)j * NDIM + j]), 0.f));
        }
    }
}

// == kernel 2: dots = x_h @ G_h (R7 config) + s^2 column-partials ===========

__global__ __launch_bounds__(NTHREADS, 1)
void main_gemm_kernel(float* __restrict__ out)
{
    extern __shared__ __align__(16) __half smem_h[];
    const int tid = threadIdx.x;
    const int m0 = blockIdx.y * BM;
    const int n0 = blockIdx.x * BN;

    auto fill = [&](int kt) {
        __half* S = smem_h + (kt % NSTAGE) * STAGE_HALVES;
        const __half* Ag = x_h + (size_t)m0 * KDIM + kt * BK;
        const __half* Bg = g_h + (size_t)n0 * KDIM + kt * BK;
        #pragma unroll
        for (int i = 0; i < 12; ++i) {
            int chunk = tid + i * NTHREADS;       // 0..3071 (16B chunks)
            int r = chunk >> 3;                   // 0..383 (A 0-127, B 128-383)
            int c = (chunk & 7) * 8;              // halves: 0,8,...,56
            const __half* src = (r < BM) ? (Ag + (size_t)r * KDIM + c)
                                         : (Bg + (size_t)(r - BM) * KDIM + c);
            CP_ASYNC16(smem_u32(S + r * LDSH + c), src);
        }
        CP_COMMIT();
    };

    const int warp = tid >> 5, lane = tid & 31;
    const int mb = (warp & 1) * 64;               // 2 warps along M
    const int nb = (warp >> 1) * 64;              // 4 warps along N
    const int wn = warp >> 1;
    const int grp = lane >> 2, tig = lane & 3;

    float d[4][8][4];
    #pragma unroll
    for (int mi = 0; mi < 4; ++mi)
        #pragma unroll
        for (int ni = 0; ni < 8; ++ni)
            #pragma unroll
            for (int r = 0; r < 4; ++r) d[mi][ni][r] = 0.f;

    fill(0); fill(1);

    for (int t = 0; t < NT; ++t) {
        if (t + 2 < NT) fill(t + 2);
        else            CP_COMMIT();              // fixed group accounting
        CP_WAIT2();
        __syncthreads();

        const __half* Asm = smem_h + (t % NSTAGE) * STAGE_HALVES;
        const __half* Bsm = Asm + BM * LDSH;

        #pragma unroll
        for (int kk = 0; kk < BK; kk += 16) {
            uint32_t a[4][4];
            #pragma unroll
            for (int mi = 0; mi < 4; ++mi) {
                const __half* p = Asm + (mb + mi * 16 + grp) * LDSH + kk + 2 * tig;
                a[mi][0] = *reinterpret_cast<const uint32_t*>(p);
                a[mi][1] = *reinterpret_cast<const uint32_t*>(p + 8 * LDSH);
                a[mi][2] = *reinterpret_cast<const uint32_t*>(p + 8);
                a[mi][3] = *reinterpret_cast<const uint32_t*>(p + 8 * LDSH + 8);
            }
            uint32_t b[8][2];
            #pragma unroll
            for (int ni = 0; ni < 8; ++ni) {
                const __half* q = Bsm + (nb + ni * 8 + grp) * LDSH + kk + 2 * tig;
                b[ni][0] = *reinterpret_cast<const uint32_t*>(q);
                b[ni][1] = *reinterpret_cast<const uint32_t*>(q + 8);
            }
            #pragma unroll
            for (int mi = 0; mi < 4; ++mi)
                #pragma unroll
                for (int ni = 0; ni < 8; ++ni)
                    mma_f16(d[mi][ni], a[mi], b[ni]);
        }
        __syncthreads();                          // also guards smem reuse below
    }

    // epilogue: raw dots + s^2 partials (deterministic, no atomics)
    float rs[4][2] = {};
    #pragma unroll
    for (int mi = 0; mi < 4; ++mi) {
        #pragma unroll
        for (int ni = 0; ni < 8; ++ni) {
            int row = m0 + mb + mi * 16 + grp;
            int col = n0 + nb + ni * 8 + 2 * tig;
            *reinterpret_cast<float2*>(out + (size_t)row * NDIM + col) =
                make_float2(d[mi][ni][0], d[mi][ni][1]);
            *reinterpret_cast<float2*>(out + (size_t)(row + 8) * NDIM + col) =
                make_float2(d[mi][ni][2], d[mi][ni][3]);
            float2 xa = __half22float2(
                *reinterpret_cast<const __half2*>(x_h + (size_t)row * NDIM + col));
            float2 xb = __half22float2(
                *reinterpret_cast<const __half2*>(x_h + (size_t)(row + 8) * NDIM + col));
            rs[mi][0] += d[mi][ni][0] * xa.x + d[mi][ni][1] * xa.y;
            rs[mi][1] += d[mi][ni][2] * xb.x + d[mi][ni][3] * xb.y;
        }
    }
    #pragma unroll
    for (int mi = 0; mi < 4; ++mi) {
        #pragma unroll
        for (int h = 0; h < 2; ++h) {
            rs[mi][h] += __shfl_xor_sync(0xffffffffu, rs[mi][h], 1);
            rs[mi][h] += __shfl_xor_sync(0xffffffffu, rs[mi][h], 2);
        }
    }
    float* s2buf = reinterpret_cast<float*>(smem_h);   // 4 x 128 floats
    if (tig == 0) {
        #pragma unroll
        for (int mi = 0; mi < 4; ++mi) {
            s2buf[wn * BM + mb + mi * 16 + grp]     = rs[mi][0];
        }
        #pragma unroll
        for (int mi = 0; mi < 4; ++mi) {
            s2buf[wn * BM + mb + mi * 16 + 8 + grp] = rs[mi][1];
        }
    }
    __syncthreads();
    if (tid < BM) {
        s2_part[blockIdx.x][m0 + tid] =
            s2buf[tid] + s2buf[BM + tid] + s2buf[2 * BM + tid] + s2buf[3 * BM + tid];
    }
}

// ================== kernel 3: s_i = sqrt(sum partials) =====================

__global__ __launch_bounds__(256)
void rowsum_kernel() {
    int m = blockIdx.x * 256 + threadIdx.x;
    float v = s2_part[0][m] + s2_part[1][m] + s2_part[2][m] + s2_part[3][m];
    s_row[m] = sqrtf(fmaxf(v, 0.f));
}

// ======= kernel 4: finalize = dots / max(s_i*e_j, eps), no x re-read =======

__global__ __launch_bounds__(256)
void finalize_kernel(float* __restrict__ out)
{
    const int m = blockIdx.x, t = threadIdx.x;
    float s = s_row[m];
    float4* dp = reinterpret_cast<float4*>(out + (size_t)m * NDIM);
    float4 dv = dp[t];
    float4 ev = reinterpret_cast<const float4*>(e_norm)[t];
    dv.x = __fdividef(dv.x, fmaxf(s * ev.x, 1e-8f));
    dv.y = __fdividef(dv.y, fmaxf(s * ev.y, 1e-8f));
    dv.z = __fdividef(dv.z, fmaxf(s * ev.z, 1e-8f));
    dv.w = __fdividef(dv.w, fmaxf(s * ev.w, 1e-8f));
    dp[t] = dv;
}

// ============================== launch =====================================

extern "C" void kernel_launch(void* const* d_in, const int* in_sizes, int n_in,
                              void* d_out, int out_size) {
    const float* x   = (const float*)d_in[0];   // [1, 65536, 1024] fp32
    const float* emb = (const float*)d_in[1];   // [1024, 1024] fp32
    float* out = (float*)d_out;                 // [1, 65536, 1024] fp32
    (void)in_sizes; (void)n_in; (void)out_size;

    cudaFuncSetAttribute(main_gemm_kernel,
                         cudaFuncAttributeMaxDynamicSharedMemorySize, SMEM_MAIN);

    // 1) prep: G (blocks 0..63, incl. e_norm) overlapped with x->fp16
    prep_kernel<<<64 + (int)((size_t)MDIM * KDIM / 2048), 256>>>(emb, x);
    // 2) dots = x_h @ G_h + s^2 partials
    main_gemm_kernel<<<dim3(NDIM / BN, MDIM / BM), NTHREADS, SMEM_MAIN>>>(out);
    // 3) s_i
    rowsum_kernel<<<MDIM / 256, 256>>>();
    // 4) out = dots / max(s_i * e_j, eps)
    finalize_kernel<<<MDIM, 256>>>(out);
}

// round 12
// speedup vs baseline: 1.0374x; 1.0374x over previous
#include <cuda_runtime.h>
#include <cuda_fp16.h>
#include <cstdint>
#include <math.h>

// ---------------------------------------------------------------------------
// SoftEmbRescore (sm_100 base ISA — tcgen05 unavailable in this build):
//   prep:  G = emb @ emb^T (tf32 mma.sync -> fp16, blocks 0..63) overlapped
//          with x_h = fp16(x) (blocks 64..); e_norm from diagonal CTAs;
//          per-m-block finalize counters reset.
//   gemm:  dots = x_h @ G_h (fp16 m16n8k16, R7 config: 128x256 CTA,
//          64x64 warp, 3-stage cp.async — at the legacy-HMMA rate ceiling).
//          Epilogue: s^2 partials with SMEM-STAGED x (coalesced; R11's
//          scattered gmem reads cost +79us), then the LAST of the 4
//          column-CTAs per m-block divides the whole 128x1024 block in
//          place (dots still L2-hot; overlaps remaining GEMM waves).
// ---------------------------------------------------------------------------

namespace {
constexpr int MDIM = 65536;
constexpr int NDIM = 1024;
constexpr int KDIM = 1024;

constexpr int BM = 128;
constexpr int BN = 256;
constexpr int BK = 64;
constexpr int LDSH = BK + 8;                     // 72 halves = 144 B rows
constexpr int NTHREADS = 256;
constexpr int NSTAGE = 3;
constexpr int NT = KDIM / BK;                    // 16
constexpr int STAGE_HALVES = (BM + BN) * LDSH;   // 27648 halves = 55296 B
constexpr int SMEM_MAIN = NSTAGE * STAGE_HALVES * 2;  // 165888 B
constexpr int NCTA_N = NDIM / BN;                // 4
constexpr int NBLK_M = MDIM / BM;                // 512
constexpr int XS = BN + 8;                       // x-tile smem stride (halves)

constexpr int GBM = 128, GBN = 128, GBK = 16;
constexpr int GLDS = GBK + 4;
constexpr int GNT = KDIM / GBK;
constexpr int GSTAGE = (GBM + GBN) * GLDS;
}

__device__ __align__(16) __half g_h[(size_t)NDIM * NDIM];     // 2 MB
__device__ __align__(16) __half x_h[(size_t)MDIM * KDIM];     // 128 MB
__device__ __align__(16) float e_norm[NDIM];
__device__ __align__(16) float s2_part[NCTA_N][MDIM];         // 1 MB
__device__ int g_cnt[NBLK_M];

// ============================ helpers ======================================

__device__ __forceinline__ uint32_t smem_u32(const void* p) {
    uint32_t a;
    asm("{ .reg .u64 t; cvta.to.shared.u64 t, %1; cvt.u32.u64 %0, t; }" : "=r"(a) : "l"(p));
    return a;
}
__device__ __forceinline__ uint32_t f2tf32(float f) {
    uint32_t r;
    asm("cvt.rna.tf32.f32 %0, %1;" : "=r"(r) : "f"(f));
    return r;
}
__device__ __forceinline__ void mma_tf32(float* d, const uint32_t* a, const uint32_t* b) {
    asm volatile(
        "mma.sync.aligned.m16n8k8.row.col.f32.tf32.tf32.f32 "
        "{%0,%1,%2,%3}, {%4,%5,%6,%7}, {%8,%9}, {%0,%1,%2,%3};"
        : "+f"(d[0]), "+f"(d[1]), "+f"(d[2]), "+f"(d[3])
        : "r"(a[0]), "r"(a[1]), "r"(a[2]), "r"(a[3]), "r"(b[0]), "r"(b[1]));
}
__device__ __forceinline__ void mma_f16(float* d, const uint32_t* a, const uint32_t* b) {
    asm volatile(
        "mma.sync.aligned.m16n8k16.row.col.f32.f16.f16.f32 "
        "{%0,%1,%2,%3}, {%4,%5,%6,%7}, {%8,%9}, {%0,%1,%2,%3};"
        : "+f"(d[0]), "+f"(d[1]), "+f"(d[2]), "+f"(d[3])
        : "r"(a[0]), "r"(a[1]), "r"(a[2]), "r"(a[3]), "r"(b[0]), "r"(b[1]));
}

#define CP_ASYNC16(dst, src) \
    asm volatile("cp.async.cg.shared.global [%0], [%1], 16;" :: "r"(dst), "l"(src))
#define CP_COMMIT() asm volatile("cp.async.commit_group;")
#define CP_WAIT2()  asm volatile("cp.async.wait_group 2;")
#define CP_WAIT1()  asm volatile("cp.async.wait_group 1;")
#define CP_WAIT0()  asm volatile("cp.async.wait_group 0;")

// ====== kernel 1: prep = {G-builder (blocks 0..63) | x->fp16 (rest)} =======

__global__ __launch_bounds__(256)
void prep_kernel(const float* __restrict__ emb, const float* __restrict__ x)
{
    __shared__ __align__(16) float smem[2 * GSTAGE];
    const int tid = threadIdx.x;

    if (blockIdx.x >= 64) {
        if (blockIdx.x == 64) {                  // reset finalize counters
            if (tid < NBLK_M) g_cnt[tid] = 0;
            if (tid + 256 < NBLK_M) g_cnt[tid + 256] = 0;
        }
        size_t i = ((size_t)(blockIdx.x - 64) * 256 + tid) * 8;
        float4 v0 = *reinterpret_cast<const float4*>(x + i);
        float4 v1 = *reinterpret_cast<const float4*>(x + i + 4);
        __half2 h[4];
        h[0] = __floats2half2_rn(v0.x, v0.y);
        h[1] = __floats2half2_rn(v0.z, v0.w);
        h[2] = __floats2half2_rn(v1.x, v1.y);
        h[3] = __floats2half2_rn(v1.z, v1.w);
        *reinterpret_cast<uint4*>(x_h + i) = *reinterpret_cast<uint4*>(h);
        return;
    }

    const int m0 = (blockIdx.x >> 3) * GBM;
    const int n0 = (blockIdx.x & 7) * GBN;
    const float* A = emb;

    auto load_stage = [&](int s, int kt) {
        const float* Ag = A + (size_t)m0 * KDIM + kt * GBK;
        const float* Bg = A + (size_t)n0 * KDIM + kt * GBK;
        float* Asm = smem + s * GSTAGE;
        float* Bsm = Asm + GBM * GLDS;
        #pragma unroll
        for (int i = 0; i < 2; ++i) {
            int chunk = tid + i * 256;
            int r = chunk >> 2;
            int c = (chunk & 3) * 4;
            CP_ASYNC16(smem_u32(Asm + r * GLDS + c), Ag + (size_t)r * KDIM + c);
            CP_ASYNC16(smem_u32(Bsm + r * GLDS + c), Bg + (size_t)r * KDIM + c);
        }
        CP_COMMIT();
    };

    const int warp = tid >> 5, lane = tid & 31;
    const int mb = (warp & 3) * 32, nb = (warp >> 2) * 64;
    const int grp = lane >> 2, tig = lane & 3;

    float d[2][8][4];
    #pragma unroll
    for (int mi = 0; mi < 2; ++mi)
        #pragma unroll
        for (int ni = 0; ni < 8; ++ni)
            #pragma unroll
            for (int r = 0; r < 4; ++r) d[mi][ni][r] = 0.f;

    load_stage(0, 0);
    for (int t = 0; t < GNT; ++t) {
        if (t + 1 < GNT) { load_stage((t + 1) & 1, t + 1); CP_WAIT1(); }
        else             { CP_WAIT0(); }
        __syncthreads();
        const float* Asm = smem + (t & 1) * GSTAGE;
        const float* Bsm = Asm + GBM * GLDS;
        #pragma unroll
        for (int kk = 0; kk < GBK; kk += 8) {
            uint32_t a[2][4];
            #pragma unroll
            for (int mi = 0; mi < 2; ++mi) {
                const float* p = Asm + (mb + mi * 16 + grp) * GLDS + kk + tig;
                a[mi][0] = f2tf32(p[0]);
                a[mi][1] = f2tf32(p[8 * GLDS]);
                a[mi][2] = f2tf32(p[4]);
                a[mi][3] = f2tf32(p[8 * GLDS + 4]);
            }
            uint32_t b[8][2];
            #pragma unroll
            for (int ni = 0; ni < 8; ++ni) {
                const float* p = Bsm + (nb + ni * 8 + grp) * GLDS + kk + tig;
                b[ni][0] = f2tf32(p[0]);
                b[ni][1] = f2tf32(p[4]);
            }
            #pragma unroll
            for (int mi = 0; mi < 2; ++mi)
                #pragma unroll
                for (int ni = 0; ni < 8; ++ni)
                    mma_tf32(d[mi][ni], a[mi], b[ni]);
        }
        __syncthreads();
    }
    #pragma unroll
    for (int mi = 0; mi < 2; ++mi) {
        #pragma unroll
        for (int ni = 0; ni < 8; ++ni) {
            int row = m0 + mb + mi * 16 + grp;
            int col = n0 + nb + ni * 8 + 2 * tig;
            *reinterpret_cast<__half2*>(g_h + (size_t)row * NDIM + col) =
                __floats2half2_rn(d[mi][ni][0], d[mi][ni][1]);
            *reinterpret_cast<__half2*>(g_h + (size_t)(row + 8) * NDIM + col) =
                __floats2half2_rn(d[mi][ni][2], d[mi][ni][3]);
        }
    }
    if (m0 == n0) {
        __syncthreads();
        if (tid < GBM) {
            int j = m0 + tid;
            e_norm[j] = sqrtf(fmaxf(__half2float(g_h[(size_t)j * NDIM + j]), 0.f));
        }
    }
}

// == kernel 2: dots = x_h @ G_h + s^2 partials + in-place finalize ==========

__global__ __launch_bounds__(NTHREADS, 1)
void main_gemm_kernel(float* __restrict__ out)
{
    extern __shared__ __align__(16) __half smem_h[];
    const int tid = threadIdx.x;
    const int m0 = blockIdx.y * BM;
    const int n0 = blockIdx.x * BN;

    auto fill = [&](int kt) {
        __half* S = smem_h + (kt % NSTAGE) * STAGE_HALVES;
        const __half* Ag = x_h + (size_t)m0 * KDIM + kt * BK;
        const __half* Bg = g_h + (size_t)n0 * KDIM + kt * BK;
        #pragma unroll
        for (int i = 0; i < 12; ++i) {
            int chunk = tid + i * NTHREADS;
            int r = chunk >> 3;
            int c = (chunk & 7) * 8;
            const __half* src = (r < BM) ? (Ag + (size_t)r * KDIM + c)
                                         : (Bg + (size_t)(r - BM) * KDIM + c);
            CP_ASYNC16(smem_u32(S + r * LDSH + c), src);
        }
        CP_COMMIT();
    };

    const int warp = tid >> 5, lane = tid & 31;
    const int mb = (warp & 1) * 64;
    const int nb = (warp >> 1) * 64;
    const int wn = warp >> 1;
    const int grp = lane >> 2, tig = lane & 3;

    float d[4][8][4];
    #pragma unroll
    for (int mi = 0; mi < 4; ++mi)
        #pragma unroll
        for (int ni = 0; ni < 8; ++ni)
            #pragma unroll
            for (int r = 0; r < 4; ++r) d[mi][ni][r] = 0.f;

    fill(0); fill(1);

    for (int t = 0; t < NT; ++t) {
        if (t + 2 < NT) fill(t + 2);
        else            CP_COMMIT();
        CP_WAIT2();
        __syncthreads();

        const __half* Asm = smem_h + (t % NSTAGE) * STAGE_HALVES;
        const __half* Bsm = Asm + BM * LDSH;

        #pragma unroll
        for (int kk = 0; kk < BK; kk += 16) {
            uint32_t a[4][4];
            #pragma unroll
            for (int mi = 0; mi < 4; ++mi) {
                const __half* p = Asm + (mb + mi * 16 + grp) * LDSH + kk + 2 * tig;
                a[mi][0] = *reinterpret_cast<const uint32_t*>(p);
                a[mi][1] = *reinterpret_cast<const uint32_t*>(p + 8 * LDSH);
                a[mi][2] = *reinterpret_cast<const uint32_t*>(p + 8);
                a[mi][3] = *reinterpret_cast<const uint32_t*>(p + 8 * LDSH + 8);
            }
            uint32_t b[8][2];
            #pragma unroll
            for (int ni = 0; ni < 8; ++ni) {
                const __half* q = Bsm + (nb + ni * 8 + grp) * LDSH + kk + 2 * tig;
                b[ni][0] = *reinterpret_cast<const uint32_t*>(q);
                b[ni][1] = *reinterpret_cast<const uint32_t*>(q + 8);
            }
            #pragma unroll
            for (int mi = 0; mi < 4; ++mi)
                #pragma unroll
                for (int ni = 0; ni < 8; ++ni)
                    mma_f16(d[mi][ni], a[mi], b[ni]);
        }
        __syncthreads();                          // all warps done with buf t
    }

    // ---- epilogue: write raw dots ----
    #pragma unroll
    for (int mi = 0; mi < 4; ++mi) {
        #pragma unroll
        for (int ni = 0; ni < 8; ++ni) {
            int row = m0 + mb + mi * 16 + grp;
            int col = n0 + nb + ni * 8 + 2 * tig;
            *reinterpret_cast<float2*>(out + (size_t)row * NDIM + col) =
                make_float2(d[mi][ni][0], d[mi][ni][1]);
            *reinterpret_cast<float2*>(out + (size_t)(row + 8) * NDIM + col) =
                make_float2(d[mi][ni][2], d[mi][ni][3]);
        }
    }

    // ---- stage x tile into smem COALESCED (pipeline buffers are free) ----
    {
        #pragma unroll
        for (int i = 0; i < 16; ++i) {
            int chunk = tid + i * NTHREADS;       // 4096 chunks of 8 halves
            int r = chunk >> 5;                   // 32 chunks/row
            int c = (chunk & 31) * 8;
            *reinterpret_cast<uint4*>(smem_h + r * XS + c) =
                *reinterpret_cast<const uint4*>(x_h + (size_t)(m0 + r) * NDIM + n0 + c);
        }
    }
    __syncthreads();

    // ---- s^2 partials from smem-staged x ----
    float rs[4][2] = {};
    #pragma unroll
    for (int mi = 0; mi < 4; ++mi) {
        #pragma unroll
        for (int ni = 0; ni < 8; ++ni) {
            int rl = mb + mi * 16 + grp;
            int cl = nb + ni * 8 + 2 * tig;
            float2 xa = __half22float2(
                *reinterpret_cast<const __half2*>(smem_h + rl * XS + cl));
            float2 xb = __half22float2(
                *reinterpret_cast<const __half2*>(smem_h + (rl + 8) * XS + cl));
            rs[mi][0] += d[mi][ni][0] * xa.x + d[mi][ni][1] * xa.y;
            rs[mi][1] += d[mi][ni][2] * xb.x + d[mi][ni][3] * xb.y;
        }
    }
    #pragma unroll
    for (int mi = 0; mi < 4; ++mi)
        #pragma unroll
        for (int h = 0; h < 2; ++h) {
            rs[mi][h] += __shfl_xor_sync(0xffffffffu, rs[mi][h], 1);
            rs[mi][h] += __shfl_xor_sync(0xffffffffu, rs[mi][h], 2);
        }

    float* s2buf = reinterpret_cast<float*>(smem_h + BM * XS);     // 512 floats
    float* s_sh  = s2buf + 4 * BM;                                  // 128 floats
    if (tig == 0) {
        #pragma unroll
        for (int mi = 0; mi < 4; ++mi) {
            s2buf[wn * BM + mb + mi * 16 + grp]     = rs[mi][0];
            s2buf[wn * BM + mb + mi * 16 + 8 + grp] = rs[mi][1];
        }
    }
    __syncthreads();
    if (tid < BM) {
        s2_part[blockIdx.x][m0 + tid] =
            s2buf[tid] + s2buf[BM + tid] + s2buf[2 * BM + tid] + s2buf[3 * BM + tid];
    }

    // ---- last column-CTA of this m-block finalizes it in place ----
    __threadfence();                               // release dots + partials
    __syncthreads();
    __shared__ int is_last;
    if (tid == 0)
        is_last = (atomicAdd(&g_cnt[blockIdx.y], 1) == NCTA_N - 1);
    __syncthreads();
    if (!is_last) return;
    __threadfence();                               // acquire peers' writes

    if (tid < BM) {
        float v = s2_part[0][m0 + tid] + s2_part[1][m0 + tid]
                + s2_part[2][m0 + tid] + s2_part[3][m0 + tid];
        s_sh[tid] = sqrtf(fmaxf(v, 0.f));
    }
    __syncthreads();

    float4 ev = reinterpret_cast<const float4*>(e_norm)[tid];   // tid -> col chunk
    #pragma unroll 4
    for (int r = 0; r < BM; ++r) {
        float s = s_sh[r];
        float4* dp = reinterpret_cast<float4*>(out + (size_t)(m0 + r) * NDIM) + tid;
        float4 dv = *dp;
        dv.x = __fdividef(dv.x, fmaxf(s * ev.x, 1e-8f));
        dv.y = __fdividef(dv.y, fmaxf(s * ev.y, 1e-8f));
        dv.z = __fdividef(dv.z, fmaxf(s * ev.z, 1e-8f));
        dv.w = __fdividef(dv.w, fmaxf(s * ev.w, 1e-8f));
        *dp = dv;
    }
}

// ============================== launch =====================================

extern "C" void kernel_launch(void* const* d_in, const int* in_sizes, int n_in,
                              void* d_out, int out_size) {
    const float* x   = (const float*)d_in[0];   // [1, 65536, 1024] fp32
    const float* emb = (const float*)d_in[1];   // [1024, 1024] fp32
    float* out = (float*)d_out;                 // [1, 65536, 1024] fp32
    (void)in_sizes; (void)n_in; (void)out_size;

    cudaFuncSetAttribute(main_gemm_kernel,
                         cudaFuncAttributeMaxDynamicSharedMemorySize, SMEM_MAIN);

    // 1) prep: G + e_norm (blocks 0..63) overlapped with x->fp16; counters reset
    prep_kernel<<<64 + (int)((size_t)MDIM * KDIM / 2048), 256>>>(emb, x);
    // 2) dots + s^2 partials + in-place finalize (last CTA per m-block)
    main_gemm_kernel<<<dim3(NCTA_N, NBLK_M), NTHREADS, SMEM_MAIN>>>(out);
}

// round 13
// speedup vs baseline: 1.1368x; 1.0959x over previous
#include <cuda_runtime.h>
#include <cuda_fp16.h>
#include <cstdint>
#include <math.h>

// ---------------------------------------------------------------------------
// SoftEmbRescore (sm_100 base ISA — tcgen05 unavailable in this build):
//   prep:  G = emb @ emb^T (tf32 mma.sync -> fp16, blocks 0..63) overlapped
//          with x_h = fp16(x) (blocks 64..); e_norm from diagonal CTAs;
//          per-m-block counters reset (graph-replay safe).
//   gemm:  dots = x_h @ G_h (fp16 m16n8k16, R7 config, at the legacy-HMMA
//          f32-accum ceiling). Epilogue: smem-staged s^2 partials, then a
//          CROSS-CTA EXCHANGE (store+fence+atomic, bounded spin) among the
//          4 column-CTAs of each m-block; every CTA then divides its
//          accumulators IN REGISTERS and writes out exactly once, final.
//          No second pass over out (R12's inline finalize cost +103us).
// ---------------------------------------------------------------------------

namespace {
constexpr int MDIM = 65536;
constexpr int NDIM = 1024;
constexpr int KDIM = 1024;

constexpr int BM = 128;
constexpr int BN = 256;
constexpr int BK = 64;
constexpr int LDSH = BK + 8;                     // 72 halves = 144 B rows
constexpr int NTHREADS = 256;
constexpr int NSTAGE = 3;
constexpr int NT = KDIM / BK;                    // 16
constexpr int STAGE_HALVES = (BM + BN) * LDSH;   // 27648 halves = 55296 B
constexpr int SMEM_MAIN = NSTAGE * STAGE_HALVES * 2;  // 165888 B
constexpr int NCTA_N = NDIM / BN;                // 4
constexpr int NBLK_M = MDIM / BM;                // 512
constexpr int XS = BN + 8;                       // x-tile smem stride (halves)

constexpr int GBM = 128, GBN = 128, GBK = 16;
constexpr int GLDS = GBK + 4;
constexpr int GNT = KDIM / GBK;
constexpr int GSTAGE = (GBM + GBN) * GLDS;
}

__device__ __align__(16) __half g_h[(size_t)NDIM * NDIM];     // 2 MB
__device__ __align__(16) __half x_h[(size_t)MDIM * KDIM];     // 128 MB
__device__ __align__(16) float e_norm[NDIM];
__device__ __align__(16) float s2_part[NCTA_N][MDIM];         // 1 MB
__device__ int g_cnt[NBLK_M];

// ============================ helpers ======================================

__device__ __forceinline__ uint32_t smem_u32(const void* p) {
    uint32_t a;
    asm("{ .reg .u64 t; cvta.to.shared.u64 t, %1; cvt.u32.u64 %0, t; }" : "=r"(a) : "l"(p));
    return a;
}
__device__ __forceinline__ uint32_t f2tf32(float f) {
    uint32_t r;
    asm("cvt.rna.tf32.f32 %0, %1;" : "=r"(r) : "f"(f));
    return r;
}
__device__ __forceinline__ void mma_tf32(float* d, const uint32_t* a, const uint32_t* b) {
    asm volatile(
        "mma.sync.aligned.m16n8k8.row.col.f32.tf32.tf32.f32 "
        "{%0,%1,%2,%3}, {%4,%5,%6,%7}, {%8,%9}, {%0,%1,%2,%3};"
        : "+f"(d[0]), "+f"(d[1]), "+f"(d[2]), "+f"(d[3])
        : "r"(a[0]), "r"(a[1]), "r"(a[2]), "r"(a[3]), "r"(b[0]), "r"(b[1]));
}
__device__ __forceinline__ void mma_f16(float* d, const uint32_t* a, const uint32_t* b) {
    asm volatile(
        "mma.sync.aligned.m16n8k16.row.col.f32.f16.f16.f32 "
        "{%0,%1,%2,%3}, {%4,%5,%6,%7}, {%8,%9}, {%0,%1,%2,%3};"
        : "+f"(d[0]), "+f"(d[1]), "+f"(d[2]), "+f"(d[3])
        : "r"(a[0]), "r"(a[1]), "r"(a[2]), "r"(a[3]), "r"(b[0]), "r"(b[1]));
}

#define CP_ASYNC16(dst, src) \
    asm volatile("cp.async.cg.shared.global [%0], [%1], 16;" :: "r"(dst), "l"(src))
#define CP_COMMIT() asm volatile("cp.async.commit_group;")
#define CP_WAIT2()  asm volatile("cp.async.wait_group 2;")
#define CP_WAIT1()  asm volatile("cp.async.wait_group 1;")
#define CP_WAIT0()  asm volatile("cp.async.wait_group 0;")

// ====== kernel 1: prep = {G-builder (blocks 0..63) | x->fp16 (rest)} =======

__global__ __launch_bounds__(256)
void prep_kernel(const float* __restrict__ emb, const float* __restrict__ x)
{
    __shared__ __align__(16) float smem[2 * GSTAGE];
    const int tid = threadIdx.x;

    if (blockIdx.x >= 64) {
        if (blockIdx.x == 64) {                  // reset exchange counters
            if (tid < NBLK_M) g_cnt[tid] = 0;
            if (tid + 256 < NBLK_M) g_cnt[tid + 256] = 0;
        }
        size_t i = ((size_t)(blockIdx.x - 64) * 256 + tid) * 8;
        float4 v0 = *reinterpret_cast<const float4*>(x + i);
        float4 v1 = *reinterpret_cast<const float4*>(x + i + 4);
        __half2 h[4];
        h[0] = __floats2half2_rn(v0.x, v0.y);
        h[1] = __floats2half2_rn(v0.z, v0.w);
        h[2] = __floats2half2_rn(v1.x, v1.y);
        h[3] = __floats2half2_rn(v1.z, v1.w);
        *reinterpret_cast<uint4*>(x_h + i) = *reinterpret_cast<uint4*>(h);
        return;
    }

    const int m0 = (blockIdx.x >> 3) * GBM;
    const int n0 = (blockIdx.x & 7) * GBN;
    const float* A = emb;

    auto load_stage = [&](int s, int kt) {
        const float* Ag = A + (size_t)m0 * KDIM + kt * GBK;
        const float* Bg = A + (size_t)n0 * KDIM + kt * GBK;
        float* Asm = smem + s * GSTAGE;
        float* Bsm = Asm + GBM * GLDS;
        #pragma unroll
        for (int i = 0; i < 2; ++i) {
            int chunk = tid + i * 256;
            int r = chunk >> 2;
            int c = (chunk & 3) * 4;
            CP_ASYNC16(smem_u32(Asm + r * GLDS + c), Ag + (size_t)r * KDIM + c);
            CP_ASYNC16(smem_u32(Bsm + r * GLDS + c), Bg + (size_t)r * KDIM + c);
        }
        CP_COMMIT();
    };

    const int warp = tid >> 5, lane = tid & 31;
    const int mb = (warp & 3) * 32, nb = (warp >> 2) * 64;
    const int grp = lane >> 2, tig = lane & 3;

    float d[2][8][4];
    #pragma unroll
    for (int mi = 0; mi < 2; ++mi)
        #pragma unroll
        for (int ni = 0; ni < 8; ++ni)
            #pragma unroll
            for (int r = 0; r < 4; ++r) d[mi][ni][r] = 0.f;

    load_stage(0, 0);
    for (int t = 0; t < GNT; ++t) {
        if (t + 1 < GNT) { load_stage((t + 1) & 1, t + 1); CP_WAIT1(); }
        else             { CP_WAIT0(); }
        __syncthreads();
        const float* Asm = smem + (t & 1) * GSTAGE;
        const float* Bsm = Asm + GBM * GLDS;
        #pragma unroll
        for (int kk = 0; kk < GBK; kk += 8) {
            uint32_t a[2][4];
            #pragma unroll
            for (int mi = 0; mi < 2; ++mi) {
                const float* p = Asm + (mb + mi * 16 + grp) * GLDS + kk + tig;
                a[mi][0] = f2tf32(p[0]);
                a[mi][1] = f2tf32(p[8 * GLDS]);
                a[mi][2] = f2tf32(p[4]);
                a[mi][3] = f2tf32(p[8 * GLDS + 4]);
            }
            uint32_t b[8][2];
            #pragma unroll
            for (int ni = 0; ni < 8; ++ni) {
                const float* p = Bsm + (nb + ni * 8 + grp) * GLDS + kk + tig;
                b[ni][0] = f2tf32(p[0]);
                b[ni][1] = f2tf32(p[4]);
            }
            #pragma unroll
            for (int mi = 0; mi < 2; ++mi)
                #pragma unroll
                for (int ni = 0; ni < 8; ++ni)
                    mma_tf32(d[mi][ni], a[mi], b[ni]);
        }
        __syncthreads();
    }
    #pragma unroll
    for (int mi = 0; mi < 2; ++mi) {
        #pragma unroll
        for (int ni = 0; ni < 8; ++ni) {
            int row = m0 + mb + mi * 16 + grp;
            int col = n0 + nb + ni * 8 + 2 * tig;
            *reinterpret_cast<__half2*>(g_h + (size_t)row * NDIM + col) =
                __floats2half2_rn(d[mi][ni][0], d[mi][ni][1]);
            *reinterpret_cast<__half2*>(g_h + (size_t)(row + 8) * NDIM + col) =
                __floats2half2_rn(d[mi][ni][2], d[mi][ni][3]);
        }
    }
    if (m0 == n0) {
        __syncthreads();
        if (tid < GBM) {
            int j = m0 + tid;
            e_norm[j] = sqrtf(fmaxf(__half2float(g_h[(size_t)j * NDIM + j]), 0.f));
        }
    }
}

// == kernel 2: dots GEMM + cross-CTA s exchange + in-register finalize ======

__global__ __launch_bounds__(NTHREADS, 1)
void main_gemm_kernel(float* __restrict__ out)
{
    extern __shared__ __align__(16) __half smem_h[];
    const int tid = threadIdx.x;
    const int m0 = blockIdx.y * BM;
    const int n0 = blockIdx.x * BN;

    auto fill = [&](int kt) {
        __half* S = smem_h + (kt % NSTAGE) * STAGE_HALVES;
        const __half* Ag = x_h + (size_t)m0 * KDIM + kt * BK;
        const __half* Bg = g_h + (size_t)n0 * KDIM + kt * BK;
        #pragma unroll
        for (int i = 0; i < 12; ++i) {
            int chunk = tid + i * NTHREADS;
            int r = chunk >> 3;
            int c = (chunk & 7) * 8;
            const __half* src = (r < BM) ? (Ag + (size_t)r * KDIM + c)
                                         : (Bg + (size_t)(r - BM) * KDIM + c);
            CP_ASYNC16(smem_u32(S + r * LDSH + c), src);
        }
        CP_COMMIT();
    };

    const int warp = tid >> 5, lane = tid & 31;
    const int mb = (warp & 1) * 64;
    const int nb = (warp >> 1) * 64;
    const int wn = warp >> 1;
    const int grp = lane >> 2, tig = lane & 3;

    float d[4][8][4];
    #pragma unroll
    for (int mi = 0; mi < 4; ++mi)
        #pragma unroll
        for (int ni = 0; ni < 8; ++ni)
            #pragma unroll
            for (int r = 0; r < 4; ++r) d[mi][ni][r] = 0.f;

    fill(0); fill(1);

    for (int t = 0; t < NT; ++t) {
        if (t + 2 < NT) fill(t + 2);
        else            CP_COMMIT();
        CP_WAIT2();
        __syncthreads();

        const __half* Asm = smem_h + (t % NSTAGE) * STAGE_HALVES;
        const __half* Bsm = Asm + BM * LDSH;

        #pragma unroll
        for (int kk = 0; kk < BK; kk += 16) {
            uint32_t a[4][4];
            #pragma unroll
            for (int mi = 0; mi < 4; ++mi) {
                const __half* p = Asm + (mb + mi * 16 + grp) * LDSH + kk + 2 * tig;
                a[mi][0] = *reinterpret_cast<const uint32_t*>(p);
                a[mi][1] = *reinterpret_cast<const uint32_t*>(p + 8 * LDSH);
                a[mi][2] = *reinterpret_cast<const uint32_t*>(p + 8);
                a[mi][3] = *reinterpret_cast<const uint32_t*>(p + 8 * LDSH + 8);
            }
            uint32_t b[8][2];
            #pragma unroll
            for (int ni = 0; ni < 8; ++ni) {
                const __half* q = Bsm + (nb + ni * 8 + grp) * LDSH + kk + 2 * tig;
                b[ni][0] = *reinterpret_cast<const uint32_t*>(q);
                b[ni][1] = *reinterpret_cast<const uint32_t*>(q + 8);
            }
            #pragma unroll
            for (int mi = 0; mi < 4; ++mi)
                #pragma unroll
                for (int ni = 0; ni < 8; ++ni)
                    mma_f16(d[mi][ni], a[mi], b[ni]);
        }
        __syncthreads();
    }

    // ---- stage this CTA's x tile into smem COALESCED ----
    #pragma unroll
    for (int i = 0; i < 16; ++i) {
        int chunk = tid + i * NTHREADS;           // 4096 chunks of 8 halves
        int r = chunk >> 5;
        int c = (chunk & 31) * 8;
        *reinterpret_cast<uint4*>(smem_h + r * XS + c) =
            *reinterpret_cast<const uint4*>(x_h + (size_t)(m0 + r) * NDIM + n0 + c);
    }
    __syncthreads();

    // ---- s^2 partial for this column tile ----
    float rs[4][2] = {};
    #pragma unroll
    for (int mi = 0; mi < 4; ++mi) {
        #pragma unroll
        for (int ni = 0; ni < 8; ++ni) {
            int rl = mb + mi * 16 + grp;
            int cl = nb + ni * 8 + 2 * tig;
            float2 xa = __half22float2(
                *reinterpret_cast<const __half2*>(smem_h + rl * XS + cl));
            float2 xb = __half22float2(
                *reinterpret_cast<const __half2*>(smem_h + (rl + 8) * XS + cl));
            rs[mi][0] += d[mi][ni][0] * xa.x + d[mi][ni][1] * xa.y;
            rs[mi][1] += d[mi][ni][2] * xb.x + d[mi][ni][3] * xb.y;
        }
    }
    #pragma unroll
    for (int mi = 0; mi < 4; ++mi)
        #pragma unroll
        for (int h = 0; h < 2; ++h) {
            rs[mi][h] += __shfl_xor_sync(0xffffffffu, rs[mi][h], 1);
            rs[mi][h] += __shfl_xor_sync(0xffffffffu, rs[mi][h], 2);
        }

    float* s2buf = reinterpret_cast<float*>(smem_h + BM * XS);     // 512 f
    float* s_sh  = s2buf + 4 * BM;                                  // 128 f
    float* e_sh  = s_sh + BM;                                       // 256 f
    if (tig == 0) {
        #pragma unroll
        for (int mi = 0; mi < 4; ++mi) {
            s2buf[wn * BM + mb + mi * 16 + grp]     = rs[mi][0];
            s2buf[wn * BM + mb + mi * 16 + 8 + grp] = rs[mi][1];
        }
    }
    e_sh[tid] = e_norm[n0 + tid];                 // stage e for my columns
    __syncthreads();
    if (tid < BM) {
        s2_part[blockIdx.x][m0 + tid] =
            s2buf[tid] + s2buf[BM + tid] + s2buf[2 * BM + tid] + s2buf[3 * BM + tid];
    }

    // ---- publish partial, wait for the other 3 column-CTAs (bounded) ----
    __threadfence();                               // release partial writes
    __syncthreads();
    if (tid == 0) {
        atomicAdd(&g_cnt[blockIdx.y], 1);
        volatile int* c = g_cnt + blockIdx.y;
        for (int it = 0; it < (1 << 22); ++it)
            if (*c >= NCTA_N) break;
        __threadfence();                           // acquire peers' partials
    }
    __syncthreads();

    // ---- s_i for the whole m-block ----
    if (tid < BM) {
        float v = s2_part[0][m0 + tid] + s2_part[1][m0 + tid]
                + s2_part[2][m0 + tid] + s2_part[3][m0 + tid];
        s_sh[tid] = sqrtf(fmaxf(v, 0.f));
    }
    __syncthreads();

    // ---- divide in registers, single finalized write of out ----
    #pragma unroll
    for (int mi = 0; mi < 4; ++mi) {
        int rl = mb + mi * 16 + grp;
        float s0 = s_sh[rl], s1 = s_sh[rl + 8];
        #pragma unroll
        for (int ni = 0; ni < 8; ++ni) {
            int cl = nb + ni * 8 + 2 * tig;
            float e0 = e_sh[cl], e1 = e_sh[cl + 1];
            int row = m0 + rl;
            int col = n0 + cl;
            float2 o0 = make_float2(
                __fdividef(d[mi][ni][0], fmaxf(s0 * e0, 1e-8f)),
                __fdividef(d[mi][ni][1], fmaxf(s0 * e1, 1e-8f)));
            float2 o1 = make_float2(
                __fdividef(d[mi][ni][2], fmaxf(s1 * e0, 1e-8f)),
                __fdividef(d[mi][ni][3], fmaxf(s1 * e1, 1e-8f)));
            *reinterpret_cast<float2*>(out + (size_t)row * NDIM + col)       = o0;
            *reinterpret_cast<float2*>(out + (size_t)(row + 8) * NDIM + col) = o1;
        }
    }
}

// ============================== launch =====================================

extern "C" void kernel_launch(void* const* d_in, const int* in_sizes, int n_in,
                              void* d_out, int out_size) {
    const float* x   = (const float*)d_in[0];   // [1, 65536, 1024] fp32
    const float* emb = (const float*)d_in[1];   // [1024, 1024] fp32
    float* out = (float*)d_out;                 // [1, 65536, 1024] fp32
    (void)in_sizes; (void)n_in; (void)out_size;

    cudaFuncSetAttribute(main_gemm_kernel,
                         cudaFuncAttributeMaxDynamicSharedMemorySize, SMEM_MAIN);

    // 1) prep: G + e_norm (blocks 0..63) overlapped with x->fp16; counters reset
    prep_kernel<<<64 + (int)((size_t)MDIM * KDIM / 2048), 256>>>(emb, x);
    // 2) dots GEMM + cross-CTA s exchange + in-register finalize, one out write
    main_gemm_kernel<<<dim3(NCTA_N, NBLK_M), NTHREADS, SMEM_MAIN>>>(out);
}